// round 1
// baseline (speedup 1.0000x reference)
#include <cuda_runtime.h>
#include <math.h>

// Problem dims (fixed by setup_inputs)
#define NMAX 400000
#define GMAX 40000
#define DD   64
#define HH   96
#define RR   3
#define VV   1024
#define CC   8
#define KDIM 384          // 3*H (relation means) + H (self)
#define TILE_N 32

// ---------------- scratch (static device bss; no runtime allocation) -----
__device__ __align__(16) float g_agg[(size_t)NMAX * RR * HH];  // 460.8 MB, reused layer1+layer2
__device__ __align__(16) float g_h1[(size_t)NMAX * HH];        // 153.6 MB
__device__ __align__(16) float g_cnt[NMAX * RR];               // counts, then inverted in place
__device__ __align__(16) float g_T1[RR * VV * HH];             // emb @ W1[r]
__device__ __align__(16) float g_T1root[VV * HH];              // emb @ root1 + b1
__device__ __align__(16) float g_gacc[GMAX * CC];
__device__ __align__(16) float g_gcnt[GMAX];

// ---------------- kernels ------------------------------------------------

__global__ void zero_kernel(int n_agg4, int n_cnt, int n_gacc, int n_gcnt) {
    int i = blockIdx.x * blockDim.x + threadIdx.x;
    int stride = gridDim.x * blockDim.x;
    float4* a4 = reinterpret_cast<float4*>(g_agg);
    float4 z = make_float4(0.f, 0.f, 0.f, 0.f);
    for (int j = i; j < n_agg4; j += stride) a4[j] = z;
    for (int j = i; j < n_cnt;  j += stride) g_cnt[j]  = 0.f;
    for (int j = i; j < n_gacc; j += stride) g_gacc[j] = 0.f;
    for (int j = i; j < n_gcnt; j += stride) g_gcnt[j] = 0.f;
}

// T1[r][v][h] = emb[v] @ W1[r];  T1root[v][h] = emb[v] @ root1 + b1[h]
__global__ void tables_kernel(const float* __restrict__ emb,
                              const float* __restrict__ W1,
                              const float* __restrict__ root1,
                              const float* __restrict__ b1, int Vr) {
    int idx = blockIdx.x * blockDim.x + threadIdx.x;
    int total = (RR + 1) * Vr * HH;
    if (idx >= total) return;
    int h = idx % HH;
    int v = (idx / HH) % Vr;
    int t = idx / (HH * Vr);           // 0..2 = relation, 3 = root
    const float* erow = emb + v * DD;
    float s = 0.f;
    if (t < RR) {
        const float* w = W1 + (size_t)t * DD * HH;
        #pragma unroll
        for (int d = 0; d < DD; d++) s += erow[d] * w[d * HH + h];
        g_T1[((size_t)t * VV + v) * HH + h] = s;
    } else {
        #pragma unroll
        for (int d = 0; d < DD; d++) s += erow[d] * root1[d * HH + h];
        g_T1root[(size_t)v * HH + h] = s + b1[h];
    }
}

// Layer-1 scatter: per edge, add T1[etype][tok[src]] into agg[dst][etype][:], count edges.
__global__ void scatter1_kernel(const int* __restrict__ ei,
                                const int* __restrict__ et,
                                const int* __restrict__ tokens, int E) {
    int warp = (blockIdx.x * blockDim.x + threadIdx.x) >> 5;
    int lane = threadIdx.x & 31;
    if (warp >= E) return;
    int src = ei[warp];
    int dst = ei[E + warp];
    int r   = et[warp];
    int tok = tokens[src];
    const float* t = g_T1 + ((size_t)r * VV + tok) * HH;
    float* a = g_agg + (size_t)dst * (RR * HH) + r * HH;
    atomicAdd(a + lane,      t[lane]);
    atomicAdd(a + lane + 32, t[lane + 32]);
    atomicAdd(a + lane + 64, t[lane + 64]);
    if (lane == 0) atomicAdd(&g_cnt[dst * RR + r], 1.0f);
}

__global__ void inv_kernel(int n) {
    int i = blockIdx.x * blockDim.x + threadIdx.x;
    if (i < n) g_cnt[i] = 1.0f / fmaxf(g_cnt[i], 1.0f);
}

// h1 = relu(sum_r agg_r * inv_r + T1root[tok]); also zeroes agg for layer-2 reuse.
__global__ void h1_kernel(const int* __restrict__ tokens, int N) {
    int idx = blockIdx.x * blockDim.x + threadIdx.x;
    if (idx >= N * HH) return;
    int n = idx / HH;
    int h = idx - n * HH;
    size_t b = (size_t)n * (RR * HH);
    float a0 = g_agg[b + h];
    float a1 = g_agg[b + HH + h];
    float a2 = g_agg[b + 2 * HH + h];
    g_agg[b + h] = 0.f;
    g_agg[b + HH + h] = 0.f;
    g_agg[b + 2 * HH + h] = 0.f;
    float v = a0 * g_cnt[n * RR] + a1 * g_cnt[n * RR + 1] + a2 * g_cnt[n * RR + 2]
            + g_T1root[(size_t)tokens[n] * HH + h];
    g_h1[(size_t)n * HH + h] = fmaxf(v, 0.f);
}

// Layer-2 scatter: per edge, add h1[src] into agg[dst][etype][:].
__global__ void scatter2_kernel(const int* __restrict__ ei,
                                const int* __restrict__ et, int E) {
    int warp = (blockIdx.x * blockDim.x + threadIdx.x) >> 5;
    int lane = threadIdx.x & 31;
    if (warp >= E) return;
    int src = ei[warp];
    int dst = ei[E + warp];
    int r   = et[warp];
    const float* t = g_h1 + (size_t)src * HH;
    float* a = g_agg + (size_t)dst * (RR * HH) + r * HH;
    atomicAdd(a + lane,      t[lane]);
    atomicAdd(a + lane + 32, t[lane + 32]);
    atomicAdd(a + lane + 64, t[lane + 64]);
}

__global__ void gcnt_kernel(const int* __restrict__ batch, int N) {
    int i = blockIdx.x * blockDim.x + threadIdx.x;
    if (i < N) atomicAdd(&g_gcnt[batch[i]], 1.0f);
}

// Layer-2 GEMM per node tile: A[32 x 384] @ Wcat[384 x 96] -> relu -> @linW -> atomic graph acc.
__global__ void layer2_kernel(const float* __restrict__ W2,
                              const float* __restrict__ root2,
                              const float* __restrict__ b2,
                              const float* __restrict__ linW,
                              const int*   __restrict__ batch,
                              int N, int numTiles) {
    extern __shared__ float sh[];
    float* sW   = sh;                          // [384*96]
    float* sA   = sW + KDIM * HH;              // [32*385] (padded)
    float* sB2  = sA + TILE_N * 385;           // [96]
    float* sLW  = sB2 + HH;                    // [96*8]

    for (int i = threadIdx.x; i < RR * HH * HH; i += blockDim.x) sW[i] = W2[i];
    for (int i = threadIdx.x; i < HH * HH;      i += blockDim.x) sW[RR * HH * HH + i] = root2[i];
    for (int i = threadIdx.x; i < HH;           i += blockDim.x) sB2[i] = b2[i];
    for (int i = threadIdx.x; i < HH * CC;      i += blockDim.x) sLW[i] = linW[i];
    __syncthreads();

    int tr = threadIdx.x >> 4;      // 0..7 : node group (4 nodes)
    int tc = threadIdx.x & 15;      // 0..15: output group (6 h)

    for (int tile = blockIdx.x; tile < numTiles; tile += gridDim.x) {
        int n0 = tile * TILE_N;
        // load A tile: k<288 -> agg*inv (means), k>=288 -> h1
        for (int i = threadIdx.x; i < TILE_N * KDIM; i += blockDim.x) {
            int ln = i / KDIM;
            int k  = i - ln * KDIM;
            int n  = n0 + ln;
            float v = 0.f;
            if (n < N) {
                if (k < RR * HH) v = g_agg[(size_t)n * (RR * HH) + k] * g_cnt[n * RR + (k / HH)];
                else             v = g_h1[(size_t)n * HH + (k - RR * HH)];
            }
            sA[ln * 385 + k] = v;
        }
        __syncthreads();

        float acc[4][6];
        #pragma unroll
        for (int i = 0; i < 4; i++)
            #pragma unroll
            for (int j = 0; j < 6; j++) acc[i][j] = 0.f;

        const float* aBase = sA + tr * 4 * 385;
        const float* wBase = sW + tc * 6;
        #pragma unroll 8
        for (int k = 0; k < KDIM; k++) {
            float a0 = aBase[k];
            float a1 = aBase[385 + k];
            float a2 = aBase[2 * 385 + k];
            float a3 = aBase[3 * 385 + k];
            const float* wr = wBase + k * HH;
            #pragma unroll
            for (int j = 0; j < 6; j++) {
                float w = wr[j];
                acc[0][j] += a0 * w;
                acc[1][j] += a1 * w;
                acc[2][j] += a2 * w;
                acc[3][j] += a3 * w;
            }
        }
        __syncthreads();  // done reading sA; reuse it for h2

        #pragma unroll
        for (int i = 0; i < 4; i++)
            #pragma unroll
            for (int j = 0; j < 6; j++) {
                int h = tc * 6 + j;
                sA[(tr * 4 + i) * 385 + h] = fmaxf(acc[i][j] + sB2[h], 0.f);
            }
        __syncthreads();

        // classifier head + graph accumulation
        for (int w = threadIdx.x; w < TILE_N * CC; w += blockDim.x) {
            int ln = w / CC;
            int c  = w - ln * CC;
            int n  = n0 + ln;
            if (n < N) {
                float s = 0.f;
                #pragma unroll
                for (int h = 0; h < HH; h++) s += sA[ln * 385 + h] * sLW[h * CC + c];
                atomicAdd(&g_gacc[batch[n] * CC + c], s);
            }
        }
        __syncthreads();
    }
}

__global__ void final_kernel(const float* __restrict__ linb, float* __restrict__ out, int G) {
    int idx = blockIdx.x * blockDim.x + threadIdx.x;
    if (idx >= G * CC) return;
    int g = idx / CC;
    int c = idx - g * CC;
    out[idx] = g_gacc[idx] / fmaxf(g_gcnt[g], 1.0f) + linb[c];
}

// ---------------- launch --------------------------------------------------

extern "C" void kernel_launch(void* const* d_in, const int* in_sizes, int n_in,
                              void* d_out, int out_size) {
    const int* tokens = (const int*)d_in[0];
    const int* ei     = (const int*)d_in[1];
    const int* et     = (const int*)d_in[2];
    const int* batch  = (const int*)d_in[3];
    // trailing 9 float inputs regardless of whether num_graphs scalar is materialized
    const float* emb   = (const float*)d_in[n_in - 9];
    const float* W1    = (const float*)d_in[n_in - 8];
    const float* root1 = (const float*)d_in[n_in - 7];
    const float* b1    = (const float*)d_in[n_in - 6];
    const float* W2    = (const float*)d_in[n_in - 5];
    const float* root2 = (const float*)d_in[n_in - 4];
    const float* b2    = (const float*)d_in[n_in - 3];
    const float* linW  = (const float*)d_in[n_in - 2];
    const float* linb  = (const float*)d_in[n_in - 1];
    float* out = (float*)d_out;

    int N = in_sizes[0];
    int E = in_sizes[2];
    int G = out_size / CC;
    int Vr = in_sizes[n_in - 9] / DD;

    // 0) zero scratch
    {
        int n_agg4 = N * (RR * HH) / 4;
        zero_kernel<<<4096, 256>>>(n_agg4, N * RR, G * CC, G);
    }
    // 1) embedding x weight tables
    {
        int total = (RR + 1) * Vr * HH;
        tables_kernel<<<(total + 255) / 256, 256>>>(emb, W1, root1, b1, Vr);
    }
    // 2) layer-1 transformed scatter + counts
    scatter1_kernel<<<(E + 7) / 8, 256>>>(ei, et, tokens, E);
    // 3) invert counts in place
    inv_kernel<<<(N * RR + 255) / 256, 256>>>(N * RR);
    // 4) h1 = relu(...) and zero agg for reuse
    h1_kernel<<<(N * HH + 255) / 256, 256>>>(tokens, N);
    // 5) layer-2 scatter of h1
    scatter2_kernel<<<(E + 7) / 8, 256>>>(ei, et, E);
    // 6) graph node counts
    gcnt_kernel<<<(N + 255) / 256, 256>>>(batch, N);
    // 7) layer-2 GEMM + relu + head + graph accumulation (persistent blocks)
    {
        static int smem_set = -1;
        int smemBytes = (KDIM * HH + TILE_N * 385 + HH + HH * CC) * (int)sizeof(float);
        if (smem_set != smemBytes) {
            cudaFuncSetAttribute(layer2_kernel, cudaFuncAttributeMaxDynamicSharedMemorySize, smemBytes);
            smem_set = smemBytes;
        }
        int numTiles = (N + TILE_N - 1) / TILE_N;
        int sms = 148;
        cudaDeviceGetAttribute(&sms, cudaDevAttrMultiProcessorCount, 0);
        int grid = numTiles < sms ? numTiles : sms;
        layer2_kernel<<<grid, 128, smemBytes>>>(W2, root2, b2, linW, batch, N, numTiles);
    }
    // 8) finalize: mean-pool divide + bias
    final_kernel<<<(G * CC + 255) / 256, 256>>>(linb, out, G);
}

// round 2
// speedup vs baseline: 4.8338x; 4.8338x over previous
#include <cuda_runtime.h>
#include <math.h>

#define DD   64
#define HH   96
#define RR   3
#define VV   1024
#define CC   8
#define NMAX 400000
#define EMAX 2000000
#define GMAX 40000
#define NSEGMAX (NMAX * RR)
#define KDIM 384
#define TILE 64
#define SCAN_BLK 2048
#define NBMAX ((NSEGMAX + SCAN_BLK - 1) / SCAN_BLK)

// ---------------- static scratch (no runtime allocation) -----------------
__device__ __align__(16) int   g_cnt[NSEGMAX];
__device__ __align__(16) int   g_off[NSEGMAX + 1];
__device__ __align__(16) int   g_cur[NSEGMAX];
__device__ __align__(16) float g_inv[NSEGMAX];
__device__ __align__(16) int   g_esrc[EMAX];
__device__ __align__(16) int   g_bsum[NBMAX + 1];
__device__ __align__(16) int   g_boff[NBMAX + 1];
__device__ __align__(16) float g_T1[RR * VV * HH];     // emb @ W1[r]
__device__ __align__(16) float g_T1r[VV * HH];         // emb @ root1 + b1
__device__ __align__(16) float g_W2p[KDIM * 128];      // [k][16 groups][8] padded (6 used)
__device__ __align__(16) float g_h1[(size_t)NMAX * HH];
__device__ __align__(16) float g_gacc[GMAX * CC];
__device__ __align__(16) float g_gcnt[GMAX];

// ---------------- small kernels ------------------------------------------

__global__ void zero_kernel(int nseg, int ngacc, int ngcnt) {
    int i = blockIdx.x * blockDim.x + threadIdx.x;
    int st = gridDim.x * blockDim.x;
    for (int j = i; j < nseg;  j += st) g_cnt[j]  = 0;
    for (int j = i; j < ngacc; j += st) g_gacc[j] = 0.f;
    for (int j = i; j < ngcnt; j += st) g_gcnt[j] = 0.f;
}

// histogram of (dst, rel) segments + per-graph node counts
__global__ void hist_kernel(const int* __restrict__ ei, const int* __restrict__ et,
                            const int* __restrict__ batch, int E, int N) {
    int i = blockIdx.x * blockDim.x + threadIdx.x;
    if (i < E) {
        int d = ei[E + i];
        int r = et[i];
        atomicAdd(&g_cnt[d * RR + r], 1);
    }
    if (i < N) atomicAdd(&g_gcnt[batch[i]], 1.0f);
}

// scan pass A: per-block sums of 2048 counters
__global__ void scanA_kernel(int nseg) {
    __shared__ int sh[256];
    int base = blockIdx.x * SCAN_BLK + threadIdx.x * 8;
    int s = 0;
    #pragma unroll
    for (int i = 0; i < 8; i++) {
        int idx = base + i;
        if (idx < nseg) s += g_cnt[idx];
    }
    sh[threadIdx.x] = s;
    __syncthreads();
    for (int o = 128; o > 0; o >>= 1) {
        if (threadIdx.x < o) sh[threadIdx.x] += sh[threadIdx.x + o];
        __syncthreads();
    }
    if (threadIdx.x == 0) g_bsum[blockIdx.x] = sh[0];
}

// scan pass B: exclusive scan of block sums (single block)
__global__ void scanB_kernel(int nb) {
    __shared__ int sh[1024];
    int carry = 0;
    for (int base = 0; base < nb; base += 1024) {
        int i = base + threadIdx.x;
        int v = (i < nb) ? g_bsum[i] : 0;
        sh[threadIdx.x] = v;
        __syncthreads();
        for (int o = 1; o < 1024; o <<= 1) {
            int t = (threadIdx.x >= o) ? sh[threadIdx.x - o] : 0;
            __syncthreads();
            sh[threadIdx.x] += t;
            __syncthreads();
        }
        if (i < nb) g_boff[i] = carry + sh[threadIdx.x] - v;
        carry += sh[1023];
        __syncthreads();
    }
}

// scan pass C: local exclusive scan + block offset -> offsets, cursors, inverse counts
__global__ void scanC_kernel(int nseg, int E) {
    __shared__ int sh[256];
    int base = blockIdx.x * SCAN_BLK + threadIdx.x * 8;
    int c[8], loc[8];
    int s = 0;
    #pragma unroll
    for (int i = 0; i < 8; i++) {
        int idx = base + i;
        c[i] = (idx < nseg) ? g_cnt[idx] : 0;
        loc[i] = s;
        s += c[i];
    }
    sh[threadIdx.x] = s;
    __syncthreads();
    for (int o = 1; o < 256; o <<= 1) {
        int t = (threadIdx.x >= o) ? sh[threadIdx.x - o] : 0;
        __syncthreads();
        sh[threadIdx.x] += t;
        __syncthreads();
    }
    int toff = g_boff[blockIdx.x] + sh[threadIdx.x] - s;
    #pragma unroll
    for (int i = 0; i < 8; i++) {
        int idx = base + i;
        if (idx < nseg) {
            int o = toff + loc[i];
            g_off[idx] = o;
            g_cur[idx] = o;
            g_inv[idx] = 1.0f / ((c[i] > 0) ? (float)c[i] : 1.0f);
        }
    }
    if (blockIdx.x == 0 && threadIdx.x == 0) g_off[nseg] = E;
}

// fill CSR: scatter src indices into segment slots
__global__ void fill_kernel(const int* __restrict__ ei, const int* __restrict__ et, int E) {
    int e = blockIdx.x * blockDim.x + threadIdx.x;
    if (e >= E) return;
    int s = ei[e];
    int d = ei[E + e];
    int r = et[e];
    int p = atomicAdd(&g_cur[d * RR + r], 1);
    g_esrc[p] = s;
}

// tables: T1[r] = emb @ W1[r]; T1r = emb @ root1 + b1; W2p = padded concat(W2, root2)
__global__ void tables_kernel(const float* __restrict__ emb, const float* __restrict__ W1,
                              const float* __restrict__ root1, const float* __restrict__ b1,
                              const float* __restrict__ W2, const float* __restrict__ root2,
                              int Vr) {
    int idx = blockIdx.x * blockDim.x + threadIdx.x;
    int total1 = (RR + 1) * Vr * HH;
    if (idx < total1) {
        int h = idx % HH;
        int v = (idx / HH) % Vr;
        int t = idx / (HH * Vr);
        const float* erow = emb + v * DD;
        float s = 0.f;
        if (t < RR) {
            const float* w = W1 + (size_t)t * DD * HH;
            #pragma unroll
            for (int d = 0; d < DD; d++) s += erow[d] * w[d * HH + h];
            g_T1[((size_t)t * VV + v) * HH + h] = s;
        } else {
            #pragma unroll
            for (int d = 0; d < DD; d++) s += erow[d] * root1[d * HH + h];
            g_T1r[(size_t)v * HH + h] = s + b1[h];
        }
        return;
    }
    int j = idx - total1;
    if (j < KDIM * HH) {
        int k = j / HH;
        int c = j - k * HH;
        float v = (k < RR * HH) ? W2[k * HH + c] : root2[(k - RR * HH) * HH + c];
        g_W2p[k * 128 + (c / 6) * 8 + (c % 6)] = v;
    }
}

// ---------------- layer 1: warp-per-node CSR gather of T1 rows ----------
__global__ void layer1_kernel(const int* __restrict__ tokens, int N) {
    int warp = (blockIdx.x * blockDim.x + threadIdx.x) >> 5;
    int lane = threadIdx.x & 31;
    if (warp >= N) return;
    int n = warp;
    int o0 = g_off[n * RR], o1 = g_off[n * RR + 1], o2 = g_off[n * RR + 2], o3 = g_off[n * RR + 3];
    float a0[3] = {0.f, 0.f, 0.f}, a1[3] = {0.f, 0.f, 0.f}, a2[3] = {0.f, 0.f, 0.f};
    for (int base = o0; base < o3; base += 32) {
        int idx = base + lane;
        int tok = 0, r = 0;
        if (idx < o3) {
            int s = g_esrc[idx];
            tok = tokens[s];
            r = (idx >= o1) + (idx >= o2);
        }
        int m = o3 - base; if (m > 32) m = 32;
        for (int j = 0; j < m; j++) {
            int t  = __shfl_sync(0xffffffffu, tok, j);
            int rr = __shfl_sync(0xffffffffu, r, j);
            const float* row = g_T1 + ((size_t)rr * VV + t) * HH;
            float v0 = row[lane], v1 = row[lane + 32], v2 = row[lane + 64];
            if (rr == 0)      { a0[0] += v0; a0[1] += v1; a0[2] += v2; }
            else if (rr == 1) { a1[0] += v0; a1[1] += v1; a1[2] += v2; }
            else              { a2[0] += v0; a2[1] += v1; a2[2] += v2; }
        }
    }
    float i0 = g_inv[n * RR], i1 = g_inv[n * RR + 1], i2 = g_inv[n * RR + 2];
    int tn = tokens[n];
    const float* rt = g_T1r + (size_t)tn * HH;
    float* hp = g_h1 + (size_t)n * HH;
    hp[lane]      = fmaxf(a0[0] * i0 + a1[0] * i1 + a2[0] * i2 + rt[lane],      0.f);
    hp[lane + 32] = fmaxf(a0[1] * i0 + a1[1] * i1 + a2[1] * i2 + rt[lane + 32], 0.f);
    hp[lane + 64] = fmaxf(a0[2] * i0 + a1[2] * i1 + a2[2] * i2 + rt[lane + 64], 0.f);
}

// ---------------- layer 2: fused gather + f32x2 GEMM + head --------------
#define FMA2(acc, a, b) asm("fma.rn.f32x2 %0, %1, %2, %0;" : "+l"(acc) : "l"(a), "l"(b))
#define PACK2(d, x)     asm("mov.b64 %0, {%1, %1};" : "=l"(d) : "f"(x))
#define UNPACK2(lo, hi, p) asm("mov.b64 {%0, %1}, %2;" : "=f"(lo), "=f"(hi) : "l"(p))

__global__ void __launch_bounds__(256, 2)
layer2_kernel(const float* __restrict__ b2, const float* __restrict__ linW,
              const int* __restrict__ batch, int N) {
    extern __shared__ float sAT[];          // [KDIM][68] then reused [TILE][100]
    __shared__ float sB2[HH];
    __shared__ float sLW[HH * CC];

    int tid = threadIdx.x;
    int lane = tid & 31;
    int w = tid >> 5;

    for (int i = tid; i < HH;      i += 256) sB2[i] = b2[i];
    for (int i = tid; i < HH * CC; i += 256) sLW[i] = linW[i];

    int n0 = blockIdx.x * TILE;

    // ---- stage 1: CSR gather -> per-rel means + self row into sAT[k][node]
    for (int it = 0; it < 8; it++) {
        int nl = w * 8 + it;
        int n = n0 + nl;
        float A[3][3] = {{0.f,0.f,0.f},{0.f,0.f,0.f},{0.f,0.f,0.f}};
        float self0 = 0.f, self1 = 0.f, self2 = 0.f;
        if (n < N) {
            int o0 = g_off[n * RR], o1 = g_off[n * RR + 1], o2 = g_off[n * RR + 2], o3 = g_off[n * RR + 3];
            for (int base = o0; base < o3; base += 32) {
                int idx = base + lane;
                int s = 0, r = 0;
                if (idx < o3) {
                    s = g_esrc[idx];
                    r = (idx >= o1) + (idx >= o2);
                }
                int m = o3 - base; if (m > 32) m = 32;
                for (int j = 0; j < m; j++) {
                    int ss = __shfl_sync(0xffffffffu, s, j);
                    int rr = __shfl_sync(0xffffffffu, r, j);
                    const float* row = g_h1 + (size_t)ss * HH;
                    float v0 = row[lane], v1 = row[lane + 32], v2 = row[lane + 64];
                    if (rr == 0)      { A[0][0] += v0; A[0][1] += v1; A[0][2] += v2; }
                    else if (rr == 1) { A[1][0] += v0; A[1][1] += v1; A[1][2] += v2; }
                    else              { A[2][0] += v0; A[2][1] += v1; A[2][2] += v2; }
                }
            }
            float iv0 = g_inv[n * RR], iv1 = g_inv[n * RR + 1], iv2 = g_inv[n * RR + 2];
            #pragma unroll
            for (int q = 0; q < 3; q++) { A[0][q] *= iv0; A[1][q] *= iv1; A[2][q] *= iv2; }
            const float* hp = g_h1 + (size_t)n * HH;
            self0 = hp[lane]; self1 = hp[lane + 32]; self2 = hp[lane + 64];
        }
        #pragma unroll
        for (int r = 0; r < 3; r++) {
            #pragma unroll
            for (int q = 0; q < 3; q++)
                sAT[(r * HH + lane + 32 * q) * 68 + nl] = A[r][q];
        }
        sAT[(288 + lane)      * 68 + nl] = self0;
        sAT[(288 + lane + 32) * 68 + nl] = self1;
        sAT[(288 + lane + 64) * 68 + nl] = self2;
    }
    __syncthreads();

    // ---- stage 2: GEMM  [64 x 384] @ [384 x 96] with f32x2 ----
    int tc = tid & 15;   // 6-output group
    int tr = tid >> 4;   // 4-node group
    unsigned long long acc[4][3];
    #pragma unroll
    for (int i = 0; i < 4; i++)
        #pragma unroll
        for (int p = 0; p < 3; p++) acc[i][p] = 0ull;

    const float* wp = g_W2p + tc * 8;
    #pragma unroll 4
    for (int k = 0; k < KDIM; k++) {
        float4 a4 = *(const float4*)(sAT + k * 68 + tr * 4);
        ulonglong2 wq = *(const ulonglong2*)(wp + k * 128);
        unsigned long long w45 = *(const unsigned long long*)(wp + k * 128 + 4);
        unsigned long long p0, p1, p2, p3;
        PACK2(p0, a4.x); PACK2(p1, a4.y); PACK2(p2, a4.z); PACK2(p3, a4.w);
        FMA2(acc[0][0], p0, wq.x); FMA2(acc[0][1], p0, wq.y); FMA2(acc[0][2], p0, w45);
        FMA2(acc[1][0], p1, wq.x); FMA2(acc[1][1], p1, wq.y); FMA2(acc[1][2], p1, w45);
        FMA2(acc[2][0], p2, wq.x); FMA2(acc[2][1], p2, wq.y); FMA2(acc[2][2], p2, w45);
        FMA2(acc[3][0], p3, wq.x); FMA2(acc[3][1], p3, wq.y); FMA2(acc[3][2], p3, w45);
    }
    __syncthreads();   // done reading sAT tile

    // ---- relu(+b2) -> h2 into reused smem [node][100] ----
    #pragma unroll
    for (int i = 0; i < 4; i++) {
        int nl = tr * 4 + i;
        #pragma unroll
        for (int p = 0; p < 3; p++) {
            float lo, hi;
            UNPACK2(lo, hi, acc[i][p]);
            int o = tc * 6 + p * 2;
            sAT[nl * 100 + o]     = fmaxf(lo + sB2[o],     0.f);
            sAT[nl * 100 + o + 1] = fmaxf(hi + sB2[o + 1], 0.f);
        }
    }
    __syncthreads();

    // ---- classifier head + per-graph accumulation ----
    for (int u = tid; u < TILE * CC; u += 256) {
        int nl = u >> 3;
        int c = u & 7;
        int n = n0 + nl;
        if (n < N) {
            float s = 0.f;
            #pragma unroll
            for (int h = 0; h < HH; h++) s += sAT[nl * 100 + h] * sLW[h * CC + c];
            atomicAdd(&g_gacc[batch[n] * CC + c], s);
        }
    }
}

__global__ void final_kernel(const float* __restrict__ linb, float* __restrict__ out, int G) {
    int idx = blockIdx.x * blockDim.x + threadIdx.x;
    if (idx >= G * CC) return;
    int g = idx / CC;
    int c = idx - g * CC;
    out[idx] = g_gacc[idx] / fmaxf(g_gcnt[g], 1.0f) + linb[c];
}

// ---------------- launch --------------------------------------------------

extern "C" void kernel_launch(void* const* d_in, const int* in_sizes, int n_in,
                              void* d_out, int out_size) {
    const int* tokens = (const int*)d_in[0];
    const int* ei     = (const int*)d_in[1];
    const int* et     = (const int*)d_in[2];
    const int* batch  = (const int*)d_in[3];
    const float* emb   = (const float*)d_in[n_in - 9];
    const float* W1    = (const float*)d_in[n_in - 8];
    const float* root1 = (const float*)d_in[n_in - 7];
    const float* b1    = (const float*)d_in[n_in - 6];
    const float* W2    = (const float*)d_in[n_in - 5];
    const float* root2 = (const float*)d_in[n_in - 4];
    const float* b2    = (const float*)d_in[n_in - 3];
    const float* linW  = (const float*)d_in[n_in - 2];
    const float* linb  = (const float*)d_in[n_in - 1];
    float* out = (float*)d_out;

    int N = in_sizes[0];
    int E = in_sizes[2];
    int G = out_size / CC;
    int Vr = in_sizes[n_in - 9] / DD;
    int nseg = N * RR;
    int nb = (nseg + SCAN_BLK - 1) / SCAN_BLK;

    // 1) zero counters / accumulators
    zero_kernel<<<1024, 256>>>(nseg, G * CC, G);
    // 2) tables (independent of CSR build)
    {
        int total = (RR + 1) * Vr * HH + KDIM * HH;
        tables_kernel<<<(total + 255) / 256, 256>>>(emb, W1, root1, b1, W2, root2, Vr);
    }
    // 3) histogram + graph counts
    {
        int mx = E > N ? E : N;
        hist_kernel<<<(mx + 255) / 256, 256>>>(ei, et, batch, E, N);
    }
    // 4-6) scan
    scanA_kernel<<<nb, 256>>>(nseg);
    scanB_kernel<<<1, 1024>>>(nb);
    scanC_kernel<<<nb, 256>>>(nseg, E);
    // 7) fill CSR
    fill_kernel<<<(E + 255) / 256, 256>>>(ei, et, E);
    // 8) layer 1 (warp per node)
    layer1_kernel<<<(N + 7) / 8, 256>>>(tokens, N);
    // 9) layer 2 fused (64-node tiles)
    {
        int smemBytes = KDIM * 68 * (int)sizeof(float);
        cudaFuncSetAttribute(layer2_kernel, cudaFuncAttributeMaxDynamicSharedMemorySize, smemBytes);
        int numTiles = (N + TILE - 1) / TILE;
        layer2_kernel<<<numTiles, 256, smemBytes>>>(b2, linW, batch, N);
    }
    // 10) finalize
    final_kernel<<<(G * CC + 255) / 256, 256>>>(linb, out, G);
}